// round 10
// baseline (speedup 1.0000x reference)
#include <cuda_runtime.h>

#define N_TOKENS 2048   // 8 * 256
#define DIM 128
#define DC 16
#define TPB 4           // tokens per block
#define GRID_BLOCKS (N_TOKENS / TPB)   // 512

__global__ void __launch_bounds__(DIM) flf_quant_k9(
    const float* __restrict__ x,      // [2048, 128]
    const float* __restrict__ W_in,   // [128, 16]
    const float* __restrict__ b_in,   // [16]
    const float* __restrict__ W_out,  // [16, 128]
    const float* __restrict__ b_out,  // [128]
    float* __restrict__ out,          // [2048*128 (+ 2048 indices)]
    int write_indices)
{
    // floats laid out as [warp][token][e]: offset = warp*64 + tok*16 + e
    __shared__ float2 sm[4][TPB][8];

    const int token0 = blockIdx.x * TPB;
    const int t = threadIdx.x;
    const int lane = t & 31;
    const int warp = t >> 5;
    const unsigned FULL = 0xFFFFFFFFu;

    const int ep  = t & 7;           // e-pair: covers e = 2*ep, 2*ep+1
    const int cpl = (t >> 3) & 3;    // 8-dim chunk within the warp's 32 dims
    const int dbase = warp * 32 + cpl * 8;

    // ---- direct x loads: 8 dims this thread needs, 4 tokens (8x LDG.128, independent) ----
    const float4* xq = reinterpret_cast<const float4*>(x + (size_t)token0 * DIM);
    const int qb = dbase >> 2;
    float4 xa0 = xq[       qb], xb0 = xq[       qb + 1];
    float4 xa1 = xq[32  +  qb], xb1 = xq[32  +  qb + 1];
    float4 xa2 = xq[64  +  qb], xb2 = xq[64  +  qb + 1];
    float4 xa3 = xq[96  +  qb], xb3 = xq[96  +  qb + 1];

    // ---- W_in as float2: W_in[d][2ep..2ep+1], d = dbase..dbase+7 (amortized over 4 tokens) ----
    const float2* Wi2 = reinterpret_cast<const float2*>(W_in);
    float2 wi[8];
    #pragma unroll
    for (int i = 0; i < 8; i++) wi[i] = Wi2[(dbase + i) * (DC / 2) + ep];

    // ---- mask-independent W_out / bias prefetch (shared by 4 tokens) ----
    float wo[DC];
    #pragma unroll
    for (int e = 0; e < DC; e++) wo[e] = W_out[e * DIM + t];
    float bo = b_out[t];

    // ---- z partials: 8 dims x 2 e x 4 tokens = 64 FMAs, 8 independent chains ----
    float2 p0 = make_float2(0.f, 0.f), p1 = make_float2(0.f, 0.f);
    float2 p2 = make_float2(0.f, 0.f), p3 = make_float2(0.f, 0.f);
    #define STEP(V0, V1, V2, V3, I) \
        p0.x = fmaf((V0), wi[I].x, p0.x); p0.y = fmaf((V0), wi[I].y, p0.y); \
        p1.x = fmaf((V1), wi[I].x, p1.x); p1.y = fmaf((V1), wi[I].y, p1.y); \
        p2.x = fmaf((V2), wi[I].x, p2.x); p2.y = fmaf((V2), wi[I].y, p2.y); \
        p3.x = fmaf((V3), wi[I].x, p3.x); p3.y = fmaf((V3), wi[I].y, p3.y);
    STEP(xa0.x, xa1.x, xa2.x, xa3.x, 0) STEP(xa0.y, xa1.y, xa2.y, xa3.y, 1)
    STEP(xa0.z, xa1.z, xa2.z, xa3.z, 2) STEP(xa0.w, xa1.w, xa2.w, xa3.w, 3)
    STEP(xb0.x, xb1.x, xb2.x, xb3.x, 4) STEP(xb0.y, xb1.y, xb2.y, xb3.y, 5)
    STEP(xb0.z, xb1.z, xb2.z, xb3.z, 6) STEP(xb0.w, xb1.w, xb2.w, xb3.w, 7)
    #undef STEP

    // ---- warp pre-reduce over the 4 chunks (xor 8, then 16): 16 shfls ----
    #define RED(P, OFF) \
        P.x += __shfl_xor_sync(FULL, P.x, OFF); \
        P.y += __shfl_xor_sync(FULL, P.y, OFF);
    RED(p0, 8) RED(p1, 8) RED(p2, 8) RED(p3, 8)
    RED(p0, 16) RED(p1, 16) RED(p2, 16) RED(p3, 16)
    #undef RED

    if (lane < 8) {
        sm[warp][0][ep] = p0;
        sm[warp][1][ep] = p1;
        sm[warp][2][ep] = p2;
        sm[warp][3][ep] = p3;
    }
    __syncthreads();

    // ---- final reduce: lane l covers tokens {l>>4, 2+(l>>4)}, dim l&15.
    //      token (l>>4) offset: tok*16 + e == lane  -> uniform addressing ----
    const float* smf = reinterpret_cast<const float*>(sm);
    const float bi = b_in[lane & 15];
    float za = ((smf[     lane] + smf[ 64 + lane]) + (smf[128 + lane] + smf[192 + lane])) + bi;
    float zb = ((smf[32 + lane] + smf[ 96 + lane]) + (smf[160 + lane] + smf[224 + lane])) + bi;

    // two ballots give all four masks; bit e = (z_e > 0); tie z==0 -> 0 (argmin lowest idx)
    unsigned bA = __ballot_sync(FULL, za > 0.0f);   // tokens 0 (lo), 1 (hi)
    unsigned bB = __ballot_sync(FULL, zb > 0.0f);   // tokens 2 (lo), 3 (hi)
    unsigned m0 = bA & 0xFFFFu, m1 = bA >> 16;
    unsigned m2 = bB & 0xFFFFu, m3 = bB >> 16;

    // ---- out dim t for 4 tokens; two accumulator chains per token ----
    float a0 = bo, c0 = 0.f, a1 = bo, c1 = 0.f;
    float a2 = bo, c2 = 0.f, a3 = bo, c3 = 0.f;
    #define ACC(E, A0, A1, A2, A3) { \
        float s0 = (m0 & (1u << (E))) ? 1.0f : -1.0f; \
        float s1 = (m1 & (1u << (E))) ? 1.0f : -1.0f; \
        float s2 = (m2 & (1u << (E))) ? 1.0f : -1.0f; \
        float s3 = (m3 & (1u << (E))) ? 1.0f : -1.0f; \
        A0 = fmaf(s0, wo[E], A0); A1 = fmaf(s1, wo[E], A1); \
        A2 = fmaf(s2, wo[E], A2); A3 = fmaf(s3, wo[E], A3); }
    ACC(0,  a0, a1, a2, a3); ACC(1,  c0, c1, c2, c3);
    ACC(2,  a0, a1, a2, a3); ACC(3,  c0, c1, c2, c3);
    ACC(4,  a0, a1, a2, a3); ACC(5,  c0, c1, c2, c3);
    ACC(6,  a0, a1, a2, a3); ACC(7,  c0, c1, c2, c3);
    ACC(8,  a0, a1, a2, a3); ACC(9,  c0, c1, c2, c3);
    ACC(10, a0, a1, a2, a3); ACC(11, c0, c1, c2, c3);
    ACC(12, a0, a1, a2, a3); ACC(13, c0, c1, c2, c3);
    ACC(14, a0, a1, a2, a3); ACC(15, c0, c1, c2, c3);
    #undef ACC

    float* op = out + (size_t)token0 * DIM;
    op[            t] = a0 + c0;
    op[    DIM  +  t] = a1 + c1;
    op[2 * DIM  +  t] = a2 + c2;
    op[3 * DIM  +  t] = a3 + c3;

    if (write_indices && t == 0) {
        float4 idx = make_float4((float)(__brev(m0) >> 16), (float)(__brev(m1) >> 16),
                                 (float)(__brev(m2) >> 16), (float)(__brev(m3) >> 16));
        *reinterpret_cast<float4*>(out + (size_t)N_TOKENS * DIM + token0) = idx;
    }
}

extern "C" void kernel_launch(void* const* d_in, const int* in_sizes, int n_in,
                              void* d_out, int out_size)
{
    const float* x     = (const float*)d_in[0];
    const float* W_in  = (const float*)d_in[1];
    const float* b_in  = (const float*)d_in[2];
    const float* W_out = (const float*)d_in[3];
    const float* b_out = (const float*)d_in[4];
    float* out = (float*)d_out;

    int write_indices = (out_size >= N_TOKENS * DIM + N_TOKENS) ? 1 : 0;

    flf_quant_k9<<<GRID_BLOCKS, DIM>>>(x, W_in, b_in, W_out, b_out, out, write_indices);
}